// round 6
// baseline (speedup 1.0000x reference)
#include <cuda_runtime.h>
#include <math.h>

#define D_MODEL 1024
#define SEQ     4096
#define NHEAD   16
#define DK      64

// Scratch (allocation-free: __device__ globals)
__device__ float g_Q[SEQ * D_MODEL];
__device__ float g_K[SEQ * D_MODEL];
__device__ float g_V[SEQ * D_MODEL];
__device__ float g_O[SEQ * D_MODEL];

// ============================================================================
// GEMM: C[M,1024] = A[M,1024] @ W[1024,1024]^T + bias   (torch Linear)
// A row-major, W row-major [out,in] -> both operands contiguous along K (NT).
// 128x128 tile, BK=8, 256 threads, 8x8 register micro-tile (split 4+4),
// register prefetch of the next K-slab to hide LDG latency.
// ============================================================================
__global__ __launch_bounds__(256, 2)
void gemm_bias_nt(const float* __restrict__ A, const float* __restrict__ W,
                  const float* __restrict__ bias, float* __restrict__ C) {
    __shared__ float As[8][128];   // As[k][m]
    __shared__ float Bs[8][128];   // Bs[k][n]

    const int tid = threadIdx.x;
    const int tx  = tid & 15;      // 0..15 -> cols
    const int ty  = tid >> 4;      // 0..15 -> rows
    const int bm  = blockIdx.y * 128;
    const int bn  = blockIdx.x * 128;

    // cooperative load mapping: 128 rows x 8 k, one float4 per thread
    const int lrow = tid >> 1;          // 0..127
    const int lcol = (tid & 1) * 4;     // 0 or 4
    const float* Ap = A + (bm + lrow) * D_MODEL + lcol;
    const float* Wp = W + (bn + lrow) * D_MODEL + lcol;

    float acc[8][8];
#pragma unroll
    for (int i = 0; i < 8; i++)
#pragma unroll
        for (int j = 0; j < 8; j++) acc[i][j] = 0.0f;

    // prefetch first slab
    float4 av = *(const float4*)Ap;
    float4 wv = *(const float4*)Wp;

    for (int k0 = 0; k0 < D_MODEL; k0 += 8) {
        __syncthreads();
        As[lcol + 0][lrow] = av.x; As[lcol + 1][lrow] = av.y;
        As[lcol + 2][lrow] = av.z; As[lcol + 3][lrow] = av.w;
        Bs[lcol + 0][lrow] = wv.x; Bs[lcol + 1][lrow] = wv.y;
        Bs[lcol + 2][lrow] = wv.z; Bs[lcol + 3][lrow] = wv.w;
        __syncthreads();

        if (k0 + 8 < D_MODEL) {   // prefetch next slab (hidden under compute)
            av = *(const float4*)(Ap + k0 + 8);
            wv = *(const float4*)(Wp + k0 + 8);
        }

#pragma unroll
        for (int k = 0; k < 8; k++) {
            float a[8], b[8];
            *(float4*)&a[0] = *(const float4*)&As[k][ty * 4];
            *(float4*)&a[4] = *(const float4*)&As[k][64 + ty * 4];
            *(float4*)&b[0] = *(const float4*)&Bs[k][tx * 4];
            *(float4*)&b[4] = *(const float4*)&Bs[k][64 + tx * 4];
#pragma unroll
            for (int i = 0; i < 8; i++)
#pragma unroll
                for (int j = 0; j < 8; j++)
                    acc[i][j] = fmaf(a[i], b[j], acc[i][j]);
        }
    }

    // epilogue: + bias, coalesced float4 stores
#pragma unroll
    for (int i = 0; i < 8; i++) {
        const int row = bm + ((i < 4) ? (ty * 4 + i) : (64 + ty * 4 + (i - 4)));
        float* Cp = C + row * D_MODEL + bn;
#pragma unroll
        for (int jh = 0; jh < 2; jh++) {
            const int cb = jh * 64 + tx * 4;
            const float4 bv = *(const float4*)(bias + bn + cb);
            float4 o;
            o.x = acc[i][jh * 4 + 0] + bv.x;
            o.y = acc[i][jh * 4 + 1] + bv.y;
            o.z = acc[i][jh * 4 + 2] + bv.z;
            o.w = acc[i][jh * 4 + 3] + bv.w;
            *(float4*)(Cp + cb) = o;
        }
    }
}

// ============================================================================
// Flash attention (fp32, non-causal). One CTA = (head, 64-query block).
// Q,K stored d-major (transposed) in smem so the QK inner loop is
// 2 conflict-free LDS.128 per 16 FFMA. P written float4 row-major, PV reads
// conflict-free. Online softmax with per-row (m,l), row stats reduced via
// shfl.xor across the 16 column-lanes.
// ============================================================================
#define SQ 68   // padded smem stride (multiple of 4 for aligned float4)

__global__ __launch_bounds__(256, 3)
void attn_kernel(const float* __restrict__ Qb, const float* __restrict__ Kb,
                 const float* __restrict__ Vb, float* __restrict__ Ob) {
    extern __shared__ float sm[];
    float* Qts = sm;                 // [64][SQ]  Qts[d*SQ + r]
    float* Kts = Qts + 64 * SQ;      // [64][SQ]  Kts[d*SQ + c]
    float* Ps  = Kts + 64 * SQ;      // [64][SQ]  Ps[r*SQ + k]
    float* Vs  = Ps  + 64 * SQ;      // [64][64]  Vs[k*64 + d]

    const int tid = threadIdx.x;
    const int tx  = tid & 15;        // column group (keys / d-dims)
    const int ty  = tid >> 4;        // row group (queries)
    const int h   = blockIdx.y;
    const int q0  = blockIdx.x * 64;
    const int c0  = h * DK;

    // Load Q tile transposed + pre-scaled by 1/sqrt(dk)
#pragma unroll
    for (int p = 0; p < 4; p++) {
        const int lin = p * 1024 + tid * 4;
        const int r  = lin >> 6;
        const int d0 = lin & 63;
        const float4 v = *(const float4*)&Qb[(q0 + r) * D_MODEL + c0 + d0];
        Qts[(d0 + 0) * SQ + r] = v.x * 0.125f;
        Qts[(d0 + 1) * SQ + r] = v.y * 0.125f;
        Qts[(d0 + 2) * SQ + r] = v.z * 0.125f;
        Qts[(d0 + 3) * SQ + r] = v.w * 0.125f;
    }

    float mrun[4], lrun[4], o[4][4];
#pragma unroll
    for (int r = 0; r < 4; r++) {
        mrun[r] = -1e30f;
        lrun[r] = 0.0f;
#pragma unroll
        for (int c = 0; c < 4; c++) o[r][c] = 0.0f;
    }

    for (int kb = 0; kb < SEQ / 64; kb++) {
        const int k0 = kb * 64;
        __syncthreads();   // previous iteration's readers of Kts/Vs/Ps done (also orders Qts on kb=0)

        // Load K (transposed) and V (direct), coalesced float4 global reads
#pragma unroll
        for (int p = 0; p < 4; p++) {
            const int lin = p * 1024 + tid * 4;
            const int c  = lin >> 6;
            const int d0 = lin & 63;
            const float4 kv = *(const float4*)&Kb[(k0 + c) * D_MODEL + c0 + d0];
            Kts[(d0 + 0) * SQ + c] = kv.x;
            Kts[(d0 + 1) * SQ + c] = kv.y;
            Kts[(d0 + 2) * SQ + c] = kv.z;
            Kts[(d0 + 3) * SQ + c] = kv.w;
            const float4 vv = *(const float4*)&Vb[(k0 + c) * D_MODEL + c0 + d0];
            *(float4*)&Vs[c * 64 + d0] = vv;
        }
        __syncthreads();

        // ---- S = (Q*scale) @ K^T  (4x4 per thread) ----
        float s[4][4];
#pragma unroll
        for (int r = 0; r < 4; r++)
#pragma unroll
            for (int c = 0; c < 4; c++) s[r][c] = 0.0f;

#pragma unroll 8
        for (int d = 0; d < 64; d++) {
            float a[4], b[4];
            *(float4*)a = *(const float4*)&Qts[d * SQ + ty * 4];
            *(float4*)b = *(const float4*)&Kts[d * SQ + tx * 4];
#pragma unroll
            for (int r = 0; r < 4; r++)
#pragma unroll
                for (int c = 0; c < 4; c++)
                    s[r][c] = fmaf(a[r], b[c], s[r][c]);
        }

        // ---- online softmax update + stage P into smem ----
#pragma unroll
        for (int r = 0; r < 4; r++) {
            float mr = fmaxf(fmaxf(s[r][0], s[r][1]), fmaxf(s[r][2], s[r][3]));
            mr = fmaxf(mr, __shfl_xor_sync(0xffffffffu, mr, 1));
            mr = fmaxf(mr, __shfl_xor_sync(0xffffffffu, mr, 2));
            mr = fmaxf(mr, __shfl_xor_sync(0xffffffffu, mr, 4));
            mr = fmaxf(mr, __shfl_xor_sync(0xffffffffu, mr, 8));
            const float mnew  = fmaxf(mrun[r], mr);
            const float alpha = __expf(mrun[r] - mnew);
            mrun[r] = mnew;

            float4 pv;
            pv.x = __expf(s[r][0] - mnew);
            pv.y = __expf(s[r][1] - mnew);
            pv.z = __expf(s[r][2] - mnew);
            pv.w = __expf(s[r][3] - mnew);
            float rs = pv.x + pv.y + pv.z + pv.w;
            rs += __shfl_xor_sync(0xffffffffu, rs, 1);
            rs += __shfl_xor_sync(0xffffffffu, rs, 2);
            rs += __shfl_xor_sync(0xffffffffu, rs, 4);
            rs += __shfl_xor_sync(0xffffffffu, rs, 8);
            lrun[r] = lrun[r] * alpha + rs;

#pragma unroll
            for (int c = 0; c < 4; c++) o[r][c] *= alpha;

            *(float4*)&Ps[(ty * 4 + r) * SQ + tx * 4] = pv;
        }
        __syncthreads();

        // ---- O += P @ V  (4x4 per thread, contraction over 64 keys) ----
#pragma unroll 4
        for (int k4 = 0; k4 < 16; k4++) {
            float a[4][4];   // a[r][i] = P[4ty+r][4k4+i]
            float v[4][4];   // v[i][c] = V[4k4+i][4tx+c]
#pragma unroll
            for (int r = 0; r < 4; r++)
                *(float4*)a[r] = *(const float4*)&Ps[(ty * 4 + r) * SQ + k4 * 4];
#pragma unroll
            for (int i = 0; i < 4; i++)
                *(float4*)v[i] = *(const float4*)&Vs[(k4 * 4 + i) * 64 + tx * 4];
#pragma unroll
            for (int r = 0; r < 4; r++)
#pragma unroll
                for (int c = 0; c < 4; c++) {
                    float acc = o[r][c];
#pragma unroll
                    for (int i = 0; i < 4; i++)
                        acc = fmaf(a[r][i], v[i][c], acc);
                    o[r][c] = acc;
                }
        }
    }

    // epilogue: O /= l, write to concat-head layout [S, D_MODEL]
#pragma unroll
    for (int r = 0; r < 4; r++) {
        const float inv = 1.0f / lrun[r];
        float4 out;
        out.x = o[r][0] * inv;
        out.y = o[r][1] * inv;
        out.z = o[r][2] * inv;
        out.w = o[r][3] * inv;
        *(float4*)&Ob[(q0 + ty * 4 + r) * D_MODEL + c0 + tx * 4] = out;
    }
}

// ============================================================================
// Launch
// ============================================================================
extern "C" void kernel_launch(void* const* d_in, const int* in_sizes, int n_in,
                              void* d_out, int out_size) {
    (void)in_sizes; (void)n_in; (void)out_size;
    const float* query = (const float*)d_in[0];
    const float* key   = (const float*)d_in[1];
    const float* value = (const float*)d_in[2];
    const float* Wq = (const float*)d_in[3];
    const float* bq = (const float*)d_in[4];
    const float* Wk = (const float*)d_in[5];
    const float* bk = (const float*)d_in[6];
    const float* Wv = (const float*)d_in[7];
    const float* bv = (const float*)d_in[8];
    const float* Wo = (const float*)d_in[9];
    const float* bo = (const float*)d_in[10];
    float* out = (float*)d_out;

    float *pQ, *pK, *pV, *pO;
    cudaGetSymbolAddress((void**)&pQ, g_Q);
    cudaGetSymbolAddress((void**)&pK, g_K);
    cudaGetSymbolAddress((void**)&pV, g_V);
    cudaGetSymbolAddress((void**)&pO, g_O);

    const int ATTN_SMEM = (3 * 64 * SQ + 64 * 64) * (int)sizeof(float);  // 68608 B
    cudaFuncSetAttribute(attn_kernel, cudaFuncAttributeMaxDynamicSharedMemorySize,
                         ATTN_SMEM);

    dim3 gg(D_MODEL / 128, SEQ / 128);   // (8, 32)
    gemm_bias_nt<<<gg, 256>>>(query, Wq, bq, pQ);
    gemm_bias_nt<<<gg, 256>>>(key,   Wk, bk, pK);
    gemm_bias_nt<<<gg, 256>>>(value, Wv, bv, pV);

    dim3 ga(SEQ / 64, NHEAD);            // (64, 16)
    attn_kernel<<<ga, 256, ATTN_SMEM>>>(pQ, pK, pV, pO);

    gemm_bias_nt<<<gg, 256>>>(pO, Wo, bo, out);
}